// round 8
// baseline (speedup 1.0000x reference)
#include <cuda_runtime.h>

// Problem constants (fixed by reference setup_inputs)
#define BATCH    8
#define H        200
#define W        200
#define C        256
#define CROP     7
#define NROIS    512

#define C4       (C / 4)                       // 64 float4 per pixel
#define NPOS     (BATCH * NROIS * CROP * CROP) // 200704 output positions
#define POS_PER_WARP  2
#define WARPS_PER_BLOCK 8
#define POS_PER_BLOCK (POS_PER_WARP * WARPS_PER_BLOCK)   // 16 -> 16KB output per block

__device__ __forceinline__ float4 lerp2d(const float4 v00, const float4 v01,
                                         const float4 v10, const float4 v11,
                                         const float fx, const float fy)
{
    float4 r;
    float t, b;
    t = v00.x + (v01.x - v00.x) * fx;  b = v10.x + (v11.x - v10.x) * fx;  r.x = t + (b - t) * fy;
    t = v00.y + (v01.y - v00.y) * fx;  b = v10.y + (v11.y - v10.y) * fx;  r.y = t + (b - t) * fy;
    t = v00.z + (v01.z - v00.z) * fx;  b = v10.z + (v11.z - v10.z) * fx;  r.z = t + (b - t) * fy;
    t = v00.w + (v01.w - v00.w) * fx;  b = v10.w + (v11.w - v10.w) * fx;  r.w = t + (b - t) * fy;
    return r;
}

__device__ __forceinline__ void stcs4(float4* p, const float4 v)
{
    asm volatile("st.global.cs.v4.f32 [%0], {%1, %2, %3, %4};"
                 :: "l"(p), "f"(v.x), "f"(v.y), "f"(v.z), "f"(v.w) : "memory");
}

__device__ __forceinline__ float4 ldg4(const float4* p)
{
    float4 v;
    asm volatile("ld.global.nc.v4.f32 {%0, %1, %2, %3}, [%4];"
                 : "=f"(v.x), "=f"(v.y), "=f"(v.z), "=f"(v.w) : "l"(p));
    return v;
}

struct PosAddr {
    int p00, p01, p10, p11;
    float fx, fy;
};

__device__ __forceinline__ PosAddr decode(const float4* __restrict__ rois, int pos)
{
    const int pix = pos % (CROP * CROP);
    const int r   = pos / (CROP * CROP);
    const int iy  = pix / CROP;
    const int ix  = pix % CROP;
    const int b   = r >> 9;

    const float4 box = __ldg(&rois[r]);

    // Match reference math exactly:
    // ys = y1*(H-1) + i * ((y2-y1)*(H-1)/(crop-1))
    const float ys = box.x * (float)(H - 1)
                   + (float)iy * ((box.z - box.x) * (float)(H - 1) / (float)(CROP - 1));
    const float xs = box.y * (float)(W - 1)
                   + (float)ix * ((box.w - box.y) * (float)(W - 1) / (float)(CROP - 1));

    const float y0f = floorf(ys);
    const float x0f = floorf(xs);

    PosAddr a;
    a.fy = ys - y0f;
    a.fx = xs - x0f;

    int y0 = (int)y0f;  y0 = min(max(y0, 0), H - 1);
    int x0 = (int)x0f;  x0 = min(max(x0, 0), W - 1);
    const int y1i = min(y0 + 1, H - 1);
    const int x1i = min(x0 + 1, W - 1);

    const int row0 = (b * H + y0)  * W;
    const int row1 = (b * H + y1i) * W;
    a.p00 = (row0 + x0)  * C4;
    a.p01 = (row0 + x1i) * C4;
    a.p10 = (row1 + x0)  * C4;
    a.p11 = (row1 + x1i) * C4;
    return a;
}

__global__ __launch_bounds__(256, 3)
void roi_crop_resize_kernel(const float4* __restrict__ img,   // [B*H*W, 64] float4
                            const float4* __restrict__ rois,  // [4096] float4
                            float4* __restrict__ out)         // [NPOS, 64] float4
{
    __shared__ float4 stage[POS_PER_BLOCK * C4];   // 16 KB: block's full output tile

    const int tid  = threadIdx.x;
    const int lane = tid & 31;
    const int warp = tid >> 5;
    const int bpos = blockIdx.x * POS_PER_BLOCK;   // first position of this block
    const int pos0 = bpos + warp * POS_PER_WARP;
    const int pos1 = pos0 + 1;

    const PosAddr A = decode(rois, pos0);
    const PosAddr B = decode(rois, pos1);

    const int ca = lane;        // float4 chunk 0..31
    const int cb = lane + 32;   // float4 chunk 32..63

    // 16 independent 128-bit loads in flight: one long 8KB read burst per warp.
    const float4 Aa00 = ldg4(&img[A.p00 + ca]);
    const float4 Aa01 = ldg4(&img[A.p01 + ca]);
    const float4 Aa10 = ldg4(&img[A.p10 + ca]);
    const float4 Aa11 = ldg4(&img[A.p11 + ca]);
    const float4 Ab00 = ldg4(&img[A.p00 + cb]);
    const float4 Ab01 = ldg4(&img[A.p01 + cb]);
    const float4 Ab10 = ldg4(&img[A.p10 + cb]);
    const float4 Ab11 = ldg4(&img[A.p11 + cb]);

    const float4 Ba00 = ldg4(&img[B.p00 + ca]);
    const float4 Ba01 = ldg4(&img[B.p01 + ca]);
    const float4 Ba10 = ldg4(&img[B.p10 + ca]);
    const float4 Ba11 = ldg4(&img[B.p11 + ca]);
    const float4 Bb00 = ldg4(&img[B.p00 + cb]);
    const float4 Bb01 = ldg4(&img[B.p01 + cb]);
    const float4 Bb10 = ldg4(&img[B.p10 + cb]);
    const float4 Bb11 = ldg4(&img[B.p11 + cb]);

    // Stage results in SMEM in exact gmem layout (conflict-free: lane-contiguous 16B)
    const int s0 = (warp * POS_PER_WARP) * C4;     // local offset of pos0's chunk row
    stage[s0 + ca]      = lerp2d(Aa00, Aa01, Aa10, Aa11, A.fx, A.fy);
    stage[s0 + cb]      = lerp2d(Ab00, Ab01, Ab10, Ab11, A.fx, A.fy);
    stage[s0 + C4 + ca] = lerp2d(Ba00, Ba01, Ba10, Ba11, B.fx, B.fy);
    stage[s0 + C4 + cb] = lerp2d(Bb00, Bb01, Bb10, Bb11, B.fx, B.fy);

    __syncthreads();

    // One contiguous 16KB write burst for the whole block (4 coalesced rounds).
    float4* obase = (float4*)out + (size_t)bpos * C4;
    #pragma unroll
    for (int i = 0; i < POS_PER_BLOCK * C4 / 256; i++) {   // 4 iterations
        const int idx = i * 256 + tid;
        stcs4(obase + idx, stage[idx]);
    }
}

extern "C" void kernel_launch(void* const* d_in, const int* in_sizes, int n_in,
                              void* d_out, int out_size)
{
    const float4* img  = (const float4*)d_in[0];   // [8,200,200,256] fp32
    const float4* rois = (const float4*)d_in[1];   // [8,512,4] fp32
    float4* out        = (float4*)d_out;           // [8,512,7,7,256] fp32

    const int blocks = NPOS / POS_PER_BLOCK;       // 200704 / 16 = 12544
    roi_crop_resize_kernel<<<blocks, 256>>>(img, rois, out);
}

// round 9
// speedup vs baseline: 1.0701x; 1.0701x over previous
#include <cuda_runtime.h>

// Problem constants (fixed by reference setup_inputs)
#define BATCH    8
#define H        200
#define W        200
#define C        256
#define CROP     7
#define NROIS    512

#define C4       (C / 4)                       // 64 float4 per pixel
#define NPOS     (BATCH * NROIS * CROP * CROP) // 200704 output positions
#define POS_PER_WARP  2
#define WARPS_PER_BLOCK 8
#define POS_PER_BLOCK (POS_PER_WARP * WARPS_PER_BLOCK)   // 16

__device__ __forceinline__ float4 lerp2d(const float4 v00, const float4 v01,
                                         const float4 v10, const float4 v11,
                                         const float fx, const float fy)
{
    float4 r;
    float t, b;
    t = v00.x + (v01.x - v00.x) * fx;  b = v10.x + (v11.x - v10.x) * fx;  r.x = t + (b - t) * fy;
    t = v00.y + (v01.y - v00.y) * fx;  b = v10.y + (v11.y - v10.y) * fx;  r.y = t + (b - t) * fy;
    t = v00.z + (v01.z - v00.z) * fx;  b = v10.z + (v11.z - v10.z) * fx;  r.z = t + (b - t) * fy;
    t = v00.w + (v01.w - v00.w) * fx;  b = v10.w + (v11.w - v10.w) * fx;  r.w = t + (b - t) * fy;
    return r;
}

__device__ __forceinline__ void stcs4(float4* p, const float4 v)
{
    asm volatile("st.global.cs.v4.f32 [%0], {%1, %2, %3, %4};"
                 :: "l"(p), "f"(v.x), "f"(v.y), "f"(v.z), "f"(v.w) : "memory");
}

__device__ __forceinline__ float4 ldg4(const float4* p)
{
    float4 v;
    asm volatile("ld.global.nc.v4.f32 {%0, %1, %2, %3}, [%4];"
                 : "=f"(v.x), "=f"(v.y), "=f"(v.z), "=f"(v.w) : "l"(p));
    return v;
}

struct PosAddr {
    int p00, p01, p10, p11;
    float fx, fy;
};

__device__ __forceinline__ PosAddr decode(const float4* __restrict__ rois, int pos)
{
    const int pix = pos % (CROP * CROP);
    const int r   = pos / (CROP * CROP);
    const int iy  = pix / CROP;
    const int ix  = pix % CROP;
    const int b   = r >> 9;

    const float4 box = __ldg(&rois[r]);

    // Match reference math exactly:
    // ys = y1*(H-1) + i * ((y2-y1)*(H-1)/(crop-1))
    const float ys = box.x * (float)(H - 1)
                   + (float)iy * ((box.z - box.x) * (float)(H - 1) / (float)(CROP - 1));
    const float xs = box.y * (float)(W - 1)
                   + (float)ix * ((box.w - box.y) * (float)(W - 1) / (float)(CROP - 1));

    const float y0f = floorf(ys);
    const float x0f = floorf(xs);

    PosAddr a;
    a.fy = ys - y0f;
    a.fx = xs - x0f;

    int y0 = (int)y0f;  y0 = min(max(y0, 0), H - 1);
    int x0 = (int)x0f;  x0 = min(max(x0, 0), W - 1);
    const int y1i = min(y0 + 1, H - 1);
    const int x1i = min(x0 + 1, W - 1);

    const int row0 = (b * H + y0)  * W;
    const int row1 = (b * H + y1i) * W;
    a.p00 = (row0 + x0)  * C4;
    a.p01 = (row0 + x1i) * C4;
    a.p10 = (row1 + x0)  * C4;
    a.p11 = (row1 + x1i) * C4;
    return a;
}

__global__ __launch_bounds__(256, 2)
void roi_crop_resize_kernel(const float4* __restrict__ img,   // [B*H*W, 64] float4
                            const float4* __restrict__ rois,  // [4096] float4
                            float4* __restrict__ out)         // [NPOS, 64] float4
{
    const int tid  = threadIdx.x;
    const int lane = tid & 31;
    const int warp = tid >> 5;
    const int pos0 = blockIdx.x * POS_PER_BLOCK + warp * POS_PER_WARP;
    const int pos1 = pos0 + 1;

    const PosAddr A = decode(rois, pos0);
    const PosAddr B = decode(rois, pos1);

    const int ca = lane;        // float4 chunk 0..31
    const int cb = lane + 32;   // float4 chunk 32..63

    // 16 independent 128-bit loads in flight: one long 8KB read burst per warp,
    // no barriers, no loop-carried deps — measured optimum on this surface.
    const float4 Aa00 = ldg4(&img[A.p00 + ca]);
    const float4 Aa01 = ldg4(&img[A.p01 + ca]);
    const float4 Aa10 = ldg4(&img[A.p10 + ca]);
    const float4 Aa11 = ldg4(&img[A.p11 + ca]);
    const float4 Ab00 = ldg4(&img[A.p00 + cb]);
    const float4 Ab01 = ldg4(&img[A.p01 + cb]);
    const float4 Ab10 = ldg4(&img[A.p10 + cb]);
    const float4 Ab11 = ldg4(&img[A.p11 + cb]);

    const float4 Ba00 = ldg4(&img[B.p00 + ca]);
    const float4 Ba01 = ldg4(&img[B.p01 + ca]);
    const float4 Ba10 = ldg4(&img[B.p10 + ca]);
    const float4 Ba11 = ldg4(&img[B.p11 + ca]);
    const float4 Bb00 = ldg4(&img[B.p00 + cb]);
    const float4 Bb01 = ldg4(&img[B.p01 + cb]);
    const float4 Bb10 = ldg4(&img[B.p10 + cb]);
    const float4 Bb11 = ldg4(&img[B.p11 + cb]);

    const float4 rA0 = lerp2d(Aa00, Aa01, Aa10, Aa11, A.fx, A.fy);
    const float4 rA1 = lerp2d(Ab00, Ab01, Ab10, Ab11, A.fx, A.fy);
    const float4 rB0 = lerp2d(Ba00, Ba01, Ba10, Ba11, B.fx, B.fy);
    const float4 rB1 = lerp2d(Bb00, Bb01, Bb10, Bb11, B.fx, B.fy);

    // One long 2KB write burst per warp, streaming (evict-first) stores.
    float4* o0 = (float4*)out + (size_t)pos0 * C4;
    float4* o1 = (float4*)out + (size_t)pos1 * C4;
    stcs4(o0 + ca, rA0);
    stcs4(o0 + cb, rA1);
    stcs4(o1 + ca, rB0);
    stcs4(o1 + cb, rB1);
}

extern "C" void kernel_launch(void* const* d_in, const int* in_sizes, int n_in,
                              void* d_out, int out_size)
{
    const float4* img  = (const float4*)d_in[0];   // [8,200,200,256] fp32
    const float4* rois = (const float4*)d_in[1];   // [8,512,4] fp32
    float4* out        = (float4*)d_out;           // [8,512,7,7,256] fp32

    const int blocks = NPOS / POS_PER_BLOCK;       // 200704 / 16 = 12544
    roi_crop_resize_kernel<<<blocks, 256>>>(img, rois, out);
}